// round 16
// baseline (speedup 1.0000x reference)
#include <cuda_runtime.h>
#include <cstdint>

#define THREADS 512
#define NWARP   (THREADS / 32)
#define KVAL    10
#define NCOLS   100000
#define NVEC    (NCOLS / 4)       // 25000 float4 per row
#define CAP     4096              // candidate buffer (uint64 keys)
#define UNR     8                 // loads in flight per thread (stream)
#define SAMPV   THREADS           // sample = first 512 float4s (2048 elems)
#define TMAXC   1024              // tournament supports c <= 1024 (else fallback)

// Monotonic bijection fp32 -> uint32 (order-preserving, no NaNs in data).
__device__ __forceinline__ unsigned flip_f32(float f) {
    unsigned u = __float_as_uint(f);
    return (u & 0x80000000u) ? ~u : (u | 0x80000000u);
}
__device__ __forceinline__ unsigned flip_bits(unsigned u) {
    return (u & 0x80000000u) ? ~u : (u | 0x80000000u);
}
__device__ __forceinline__ float unflip_f32(unsigned u) {
    unsigned b = (u & 0x80000000u) ? (u ^ 0x80000000u) : ~u;
    return __uint_as_float(b);
}
// key = (flip(v)<<32) | ~idx : u64 max == larger value, then smaller index.
__device__ __forceinline__ unsigned long long mk_key(float v, int idx) {
    return ((unsigned long long)flip_f32(v) << 32) | (unsigned)(~idx);
}
__device__ __forceinline__ unsigned long long mk_key_bits(int bits, int idx) {
    return ((unsigned long long)flip_bits((unsigned)bits) << 32) | (unsigned)(~idx);
}

// 3-way signed max (DPX on sm_90+: single VIMNMX3)
__device__ __forceinline__ int max3(int a, int b, int c) {
#if __CUDA_ARCH__ >= 900
    return __vimax3_s32(a, b, c);
#else
    return max(max(a, b), c);
#endif
}
__device__ __forceinline__ int vmax4(int4 q) {      // 2 DPX-class ops
    return max(max3(q.x, q.y, q.z), q.w);
}

// Warp-collective (warp 0): over 256-bin hist, find largest bin b with
// suffix-count(>=b) >= K. Returns b; *above = count strictly above bin b.
__device__ __forceinline__ int hist_find(const int* hist, int K, int lane,
                                         int* above) {
    int h[8]; int s = 0;
    #pragma unroll
    for (int t = 0; t < 8; t++) { h[t] = hist[lane * 8 + t]; s += h[t]; }
    int cum = s;
    #pragma unroll
    for (int o = 1; o < 32; o <<= 1) {
        int t = __shfl_down_sync(0xffffffffu, cum, o);
        if (lane + o < 32) cum += t;
    }
    unsigned bal = __ballot_sync(0xffffffffu, cum >= K);
    int lstar = 31 - __clz(bal);
    int nxt = (lstar < 31) ? lstar + 1 : 0;
    int above_lane = __shfl_sync(0xffffffffu, cum, nxt);
    if (lstar == 31) above_lane = 0;
    int bin = -1, abv = 0, acc = above_lane;
    if (lane == lstar) {
        #pragma unroll
        for (int t = 7; t >= 0; t--) {
            bool hit = (bin < 0) && (acc + h[t] >= K);
            if (hit) { bin = lane * 8 + t; abv = acc; }
            acc += h[t];
        }
    }
    bin  = __shfl_sync(0xffffffffu, bin, lstar);
    *above = __shfl_sync(0xffffffffu, abv, lstar);
    return bin;
}

__global__ __launch_bounds__(THREADS, 2)
void topk_kernel(const float* __restrict__ scores, float* __restrict__ out, int B) {
    __shared__ unsigned long long s_buf[CAP];               // 32 KB
    __shared__ unsigned long long s_warp10[4 * KVAL];       // 40 keys
    __shared__ unsigned long long s_top[KVAL];
    __shared__ unsigned long long s_wbest[NWARP];
    __shared__ int                s_wpos[NWARP];
    __shared__ int                s_hist1[256];
    __shared__ int                s_hist2[256];
    __shared__ int                s_count;
    __shared__ int                s_over;
    __shared__ unsigned           s_thr;
    __shared__ int                s_b1, s_r;

    const int tid  = threadIdx.x;
    const int lane = tid & 31;
    const int wid  = tid >> 5;
    const int row  = blockIdx.x;
    const float* __restrict__ rp = scores + (size_t)row * NCOLS;
    const float4* __restrict__ r4 = (const float4*)rp;
    const int4*   __restrict__ r4i = (const int4*)rp;

    // ---- exact selection-with-removal (FALLBACK PATH ONLY) ----
    auto prune = [&]() {
        const int c = min(s_count, CAP);
        #pragma unroll 1
        for (int sel = 0; sel < KVAL; sel++) {
            unsigned long long best = 0ull; int bpos = -1;
            for (int j = tid; j < c; j += THREADS) {
                unsigned long long k = s_buf[j];
                if (k > best) { best = k; bpos = j; }
            }
            #pragma unroll
            for (int o = 16; o > 0; o >>= 1) {
                unsigned long long ob = __shfl_down_sync(0xffffffffu, best, o);
                int op               = __shfl_down_sync(0xffffffffu, bpos, o);
                if (ob > best) { best = ob; bpos = op; }
            }
            if (lane == 0) { s_wbest[wid] = best; s_wpos[wid] = bpos; }
            __syncthreads();
            if (tid == 0) {
                unsigned long long bb = 0ull; int bp = -1;
                #pragma unroll
                for (int w = 0; w < NWARP; w++)
                    if (s_wbest[w] > bb) { bb = s_wbest[w]; bp = s_wpos[w]; }
                s_top[sel] = bb;
                if (bp >= 0) s_buf[bp] = 0ull;
            }
            __syncthreads();
        }
        if (tid < KVAL) s_buf[tid] = s_top[tid];
        if (tid == 0) { s_count = KVAL; s_thr = (unsigned)(s_top[KVAL - 1] >> 32); }
        __syncthreads();
    };

    // ================= phase 0: histogram threshold from 2048-elem sample ====
    if (tid < 256) { s_hist1[tid] = 0; s_hist2[tid] = 0; }
    if (tid == 0)  { s_count = 0; s_over = 0; }
    __syncthreads();

    const float4 v0 = __ldcs(&r4[tid]);
    unsigned f0[4] = { flip_f32(v0.x), flip_f32(v0.y), flip_f32(v0.z), flip_f32(v0.w) };
    #pragma unroll
    for (int e = 0; e < 4; e++) atomicAdd(&s_hist1[f0[e] >> 24], 1);
    __syncthreads();

    if (wid == 0) {
        int above1;
        int b1 = hist_find(s_hist1, KVAL, lane, &above1);
        if (lane == 0) { s_b1 = b1; s_r = KVAL - above1; }
    }
    __syncthreads();

    const int b1 = s_b1;
    #pragma unroll
    for (int e = 0; e < 4; e++)
        if ((int)(f0[e] >> 24) == b1) atomicAdd(&s_hist2[(f0[e] >> 16) & 0xFF], 1);
    __syncthreads();

    if (wid == 0) {
        int above2;
        int b2 = hist_find(s_hist2, s_r, lane, &above2);
        if (lane == 0) s_thr = ((unsigned)b1 << 24) | ((unsigned)b2 << 16);
    }
    __syncthreads();

    const unsigned thr_u = s_thr;
    const float    thr_f = unflip_f32(thr_u);
    const int      thr_i = __float_as_int(thr_f);
    // int-domain compare trick requires positive threshold
    const bool     int_ok = (thr_f > 0.0f);
    if (!int_ok && tid == 0) s_over = 1;     // route to exact fallback

    // append sample survivors (>=10 guaranteed by construction)
    #pragma unroll
    for (int e = 0; e < 4; e++) {
        if (f0[e] >= thr_u) {
            int p = atomicAdd(&s_count, 1);
            if (p < CAP) s_buf[p] = ((unsigned long long)f0[e] << 32)
                                  | (unsigned)(~(4 * tid + e));
            else         s_over = 1;
        }
    }

    // push survivors of one vector (int-bits domain)
    auto pushv = [&](int4 q, int gi) {
        if (q.x >= thr_i) { int p = atomicAdd(&s_count, 1);
            if (p < CAP) s_buf[p] = mk_key_bits(q.x, gi + 0); else s_over = 1; }
        if (q.y >= thr_i) { int p = atomicAdd(&s_count, 1);
            if (p < CAP) s_buf[p] = mk_key_bits(q.y, gi + 1); else s_over = 1; }
        if (q.z >= thr_i) { int p = atomicAdd(&s_count, 1);
            if (p < CAP) s_buf[p] = mk_key_bits(q.z, gi + 2); else s_over = 1; }
        if (q.w >= thr_i) { int p = atomicAdd(&s_count, 1);
            if (p < CAP) s_buf[p] = mk_key_bits(q.w, gi + 3); else s_over = 1; }
    };
    // process a subgroup of 4 vectors: 1 group test, then per-vector rare body
    auto subgroup = [&](int4* v, int base) {
        int m0 = vmax4(v[0]), m1 = vmax4(v[1]), m2 = vmax4(v[2]), m3 = vmax4(v[3]);
        if (max(max3(m0, m1, m2), m3) >= thr_i) {
            if (m0 >= thr_i) pushv(v[0], (base + 0 * THREADS) * 4);
            if (m1 >= thr_i) pushv(v[1], (base + 1 * THREADS) * 4);
            if (m2 >= thr_i) pushv(v[2], (base + 2 * THREADS) * 4);
            if (m3 >= thr_i) pushv(v[3], (base + 3 * THREADS) * 4);
        }
    };

    // ================= stream: 8 LDG.128 in flight =============
    if (int_ok) {
        #pragma unroll 1
        for (int blk = 0; blk < 5; blk++) {
            const int base = SAMPV + blk * (UNR * THREADS) + tid;
            int4 v[UNR];
            #pragma unroll
            for (int u = 0; u < UNR; u++) v[u] = __ldcs(&r4i[base + u * THREADS]);
            subgroup(v,     base);
            subgroup(v + 4, base + 4 * THREADS);
        }
        {   // tail block, per-vector predicated
            const int base = SAMPV + 5 * (UNR * THREADS) + tid;   // 20992 + tid
            int4 v[UNR]; int iv[UNR]; bool ok[UNR];
            #pragma unroll
            for (int u = 0; u < UNR; u++) {
                int i = base + u * THREADS;
                ok[u] = (i < NVEC);
                iv[u] = ok[u] ? i : (NVEC - 1);
                v[u]  = __ldcs(&r4i[iv[u]]);
            }
            #pragma unroll
            for (int u = 0; u < UNR; u++) {
                if (!ok[u]) continue;
                if (vmax4(v[u]) >= thr_i) pushv(v[u], iv[u] * 4);
            }
        }
    }
    __syncthreads();

    const int  c          = min(s_count, CAP);
    const bool overflowed = (s_over != 0) || (c > TMAXC);

    if (!overflowed) {
        // ====== final: stage 1 on 4 warps (c<=1024), stage 2 on warp 0 =======
        if (tid < 128) {
            unsigned long long L[8];
            #pragma unroll
            for (int r = 0; r < 8; r++) {
                int j = tid + r * 128;
                L[r] = (j < c) ? s_buf[j] : 0ull;
            }
            #pragma unroll 1
            for (int round = 0; round < KVAL; round++) {
                unsigned long long best = 0ull; int bslot = 0;
                #pragma unroll
                for (int r = 0; r < 8; r++)
                    if (L[r] > best) { best = L[r]; bslot = r; }
                unsigned long long b = best; int who = lane;
                #pragma unroll
                for (int o = 16; o > 0; o >>= 1) {
                    unsigned long long ob = __shfl_down_sync(0xffffffffu, b, o);
                    int ow               = __shfl_down_sync(0xffffffffu, who, o);
                    if (ob > b) { b = ob; who = ow; }
                }
                b   = __shfl_sync(0xffffffffu, b, 0);
                who = __shfl_sync(0xffffffffu, who, 0);
                if (lane == who) L[bslot] = 0ull;          // remove winner
                if (lane == 0) s_warp10[wid * KVAL + round] = b;
            }
        }
        __syncthreads();
        if (wid == 0) {                                    // 40 -> top-10
            unsigned long long M[2];
            M[0] = (lane      < 40) ? s_warp10[lane]      : 0ull;
            M[1] = (lane + 32 < 40) ? s_warp10[lane + 32] : 0ull;
            #pragma unroll 1
            for (int round = 0; round < KVAL; round++) {
                unsigned long long best; int bslot;
                if (M[0] >= M[1]) { best = M[0]; bslot = 0; }
                else              { best = M[1]; bslot = 1; }
                unsigned long long b = best; int who = lane;
                #pragma unroll
                for (int o = 16; o > 0; o >>= 1) {
                    unsigned long long ob = __shfl_down_sync(0xffffffffu, b, o);
                    int ow               = __shfl_down_sync(0xffffffffu, who, o);
                    if (ob > b) { b = ob; who = ow; }
                }
                b   = __shfl_sync(0xffffffffu, b, 0);
                who = __shfl_sync(0xffffffffu, who, 0);
                if (lane == who) M[bslot] = 0ull;
                if (lane == 0) s_top[round] = b;
            }
        }
        __syncthreads();
    } else {
        // ============== correctness fallback: serial tiles + exact prunes ====
        if (tid == 0) { s_count = 0; s_thr = 0u; }
        __syncthreads();
        unsigned thr2 = 0u;
        #pragma unroll 1
        for (int basei = 0; basei < NVEC; basei += THREADS) {
            const int i = basei + tid;
            if (i < NVEC) {
                float4 q = __ldcs(&r4[i]);
                float  m = fmaxf(fmaxf(q.x, q.y), fmaxf(q.z, q.w));
                if (flip_f32(m) >= thr2) {
                    const int gi = i * 4;
                    float qv[4] = {q.x, q.y, q.z, q.w};
                    #pragma unroll
                    for (int e = 0; e < 4; e++) {
                        if (flip_f32(qv[e]) >= thr2) {
                            int p = atomicAdd(&s_count, 1);
                            if (p < CAP) s_buf[p] = mk_key(qv[e], gi + e);
                        }
                    }
                }
            }
            __syncthreads();
            const int cc = s_count;
            __syncthreads();
            if (cc >= CAP - THREADS * 4) prune();
            thr2 = s_thr;
        }
        __syncthreads();
        prune();
    }

    // ---- write out: [B*K indices (as float)] then [B*K scores]
    if (tid < KVAL) {
        unsigned long long key = s_top[tid];
        float val = unflip_f32((unsigned)(key >> 32));
        int   idx = (int)(~(unsigned)key);
        out[(size_t)row * KVAL + tid]                    = (float)idx;
        out[(size_t)B * KVAL + (size_t)row * KVAL + tid] = val;
    }
}

extern "C" void kernel_launch(void* const* d_in, const int* in_sizes, int n_in,
                              void* d_out, int out_size) {
    const float* scores = (const float*)d_in[0];
    const int B = in_sizes[0] / NCOLS;          // 2048
    (void)n_in; (void)out_size;
    topk_kernel<<<B, THREADS>>>(scores, (float*)d_out, B);
}